// round 13
// baseline (speedup 1.0000x reference)
#include <cuda_runtime.h>
#include <math.h>
#include <stdint.h>

#define CC   128
#define NPTS 4096
#define TN   64
#define NG   16
#define OPT  8
#define OP2  4
#define NSL  2
#define NTHR 512
#define EPSV 1e-12f

typedef unsigned long long ull;

// Pre-expanded (se3) + transposed weights: Wt[c][o] = W[o][c]
__device__ float g_W1t [CC * CC];
__device__ float g_W2t [CC * CC];
__device__ float g_W3t [2 * CC * CC];
__device__ float g_svWt[CC * CC];
__device__ float g_vsdWt[CC * CC];
__device__ float g_vsWt[CC * CC];
__device__ float g_ssWt[CC * CC];

__global__ void prep_kernel(const float* __restrict__ weight,
                            const float* __restrict__ sv_W,
                            const float* __restrict__ cross_weight,
                            const float* __restrict__ crossfc_weight,
                            const float* __restrict__ vsdir_weight,
                            const float* __restrict__ vs_W,
                            const float* __restrict__ ss_W)
{
    const int o = blockIdx.x;
    const int t = threadIdx.x;
    __shared__ float sred[128];

    float w = (t < CC - 1) ? weight[o * (CC - 1) + t] : 0.f;
    sred[t] = w; __syncthreads();
    for (int k = 64; k > 0; k >>= 1) { if (t < k) sred[t] += sred[t + k]; __syncthreads(); }
    float rs1 = sred[0]; __syncthreads();
    if (t < CC - 1) g_W1t[t * CC + o] = w;
    else            g_W1t[(CC - 1) * CC + o] = 1.f - rs1;

    float w2 = (t < CC - 1) ? cross_weight[o * (CC - 1) + t] : 0.f;
    sred[t] = w2; __syncthreads();
    for (int k = 64; k > 0; k >>= 1) { if (t < k) sred[t] += sred[t + k]; __syncthreads(); }
    float rs2 = sred[0]; __syncthreads();
    if (t < CC - 1) g_W2t[t * CC + o] = w2;
    else            g_W2t[(CC - 1) * CC + o] = 1.f - rs2;

    float a0 = crossfc_weight[o * (2 * CC - 1) + t];
    float a1 = (t < CC - 1) ? crossfc_weight[o * (2 * CC - 1) + CC + t] : 0.f;
    sred[t] = a0 + a1; __syncthreads();
    for (int k = 64; k > 0; k >>= 1) { if (t < k) sred[t] += sred[t + k]; __syncthreads(); }
    float rs3 = sred[0]; __syncthreads();
    g_W3t[t * CC + o] = a0;
    if (t < CC - 1) g_W3t[(CC + t) * CC + o] = a1;
    else            g_W3t[(2 * CC - 1) * CC + o] = 1.f - rs3;

    g_svWt [t * CC + o] = sv_W        [o * CC + t];
    g_vsdWt[t * CC + o] = vsdir_weight[o * CC + t];
    g_vsWt [t * CC + o] = vs_W        [o * CC + t];
    g_ssWt [t * CC + o] = ss_W        [o * CC + t];
}

// ---- packed f32x2 helpers ----
#define FMA2(acc, w, x) \
    asm("fma.rn.f32x2 %0, %1, %2, %3;" : "=l"(acc) : "l"(w), "l"(x), "l"(acc))
#define ADD2(d, a, b) \
    asm("add.rn.f32x2 %0, %1, %2;" : "=l"(d) : "l"(a), "l"(b))
#define PACK_DUP(out, x) \
    asm("mov.b64 %0, {%1, %1};" : "=l"(out) : "r"(__float_as_uint(x)))

__device__ __forceinline__ float lo2(ull v) { return __uint_as_float((unsigned)v); }
__device__ __forceinline__ float hi2(ull v) { return __uint_as_float((unsigned)(v >> 32)); }
__device__ __forceinline__ ull pack2(float lo, float hi) {
    return (ull)__float_as_uint(lo) | ((ull)__float_as_uint(hi) << 32);
}
__device__ __forceinline__ ull lds2(const float* p) { return *(const ull*)p; }
__device__ __forceinline__ void sts2(float* p, ull v) { *(ull*)p = v; }

// 1 / max(sqrt(x), EPSV) == rsqrt(max(x, EPSV^2))  (sqrt is monotone)
__device__ __forceinline__ float rsq_guard(float x) {
    return rsqrtf(fmaxf(x, 1e-24f));
}

// Load 8 consecutive transposed-weight floats as 4 packed u64 (2x LDG.128).
__device__ __forceinline__ void load_w4x2(const float* __restrict__ base, ull* w2)
{
    const ulonglong2* p = (const ulonglong2*)base;
    ulonglong2 a = p[0], b = p[1];
    w2[0] = a.x; w2[1] = a.y; w2[2] = b.x; w2[3] = b.y;
}

// GEMM over 3-vector tile S[384][TN]; accumulate 8 out-ch x 3 comps x 2 slots.
// unroll 4: ~4-k-step static window to hoist weight LDGs a full L2 latency.
template<bool INIT>
__device__ __forceinline__ void gemm3(const float* __restrict__ Wt,
                                      const float* __restrict__ S,
                                      int cb, int ob,
                                      ull aX[NSL][OP2], ull aY[NSL][OP2], ull aZ[NSL][OP2])
{
    if (INIT) {
        #pragma unroll
        for (int s = 0; s < NSL; s++)
            #pragma unroll
            for (int j = 0; j < OP2; j++) { aX[s][j] = 0; aY[s][j] = 0; aZ[s][j] = 0; }
    }
    #pragma unroll 4
    for (int c = 0; c < CC; c++) {
        ull xp = lds2(&S[(3 * c + 0) * TN + cb]);
        ull yp = lds2(&S[(3 * c + 1) * TN + cb]);
        ull zp = lds2(&S[(3 * c + 2) * TN + cb]);
        ull x0, x1, y0, y1, z0, z1;
        PACK_DUP(x0, lo2(xp)); PACK_DUP(x1, hi2(xp));
        PACK_DUP(y0, lo2(yp)); PACK_DUP(y1, hi2(yp));
        PACK_DUP(z0, lo2(zp)); PACK_DUP(z1, hi2(zp));
        ull w2[OP2]; load_w4x2(&Wt[c * CC + ob], w2);
        #pragma unroll
        for (int j = 0; j < OP2; j++) {
            FMA2(aX[0][j], w2[j], x0); FMA2(aX[1][j], w2[j], x1);
            FMA2(aY[0][j], w2[j], y0); FMA2(aY[1][j], w2[j], y1);
            FMA2(aZ[0][j], w2[j], z0); FMA2(aZ[1][j], w2[j], z1);
        }
    }
}

// value of channel (ob + jj) for slot s from packed accumulators
#define GETA(arr, s, jj) ((jj & 1) ? hi2(arr[s][jj >> 1]) : lo2(arr[s][jj >> 1]))

// ---------------------------------------------------------------------------
// Fused kernel: one block = one (b, 64-point) tile. 512 threads, 1 block/SM.
// Each thread: 8 output channels (og 0..15) x 2 adjacent points (cb, cb+1).
// ---------------------------------------------------------------------------
__global__ void __launch_bounds__(NTHR, 1)
fused_kernel(const float* __restrict__ v_in, const float* __restrict__ s_in,
             const float* __restrict__ sv_b, const float* __restrict__ vs_b,
             const float* __restrict__ ss_b, float* __restrict__ out, int B)
{
    extern __shared__ float sm[];
    float* A   = sm;                     // [384][64]  x_c, later v_cross
    float* Bm  = sm + 3 * CC * TN;       // [384][64]  s+p, later v1
    float* red = sm + 6 * CC * TN;       // [96][64]

    const int tid = threadIdx.x;
    const int nl  = tid & 31;
    const int og  = tid >> 5;            // 0..15
    const int ob  = og * OPT;
    const int cb  = nl * 2;              // column base (2 adjacent points)

    const int b  = blockIdx.x >> 6;      // 64 tiles per batch
    const int n0 = (blockIdx.x & 63) * TN;

    // ---- load x -> A, s -> Bm[0:128] (coalesced over 64 cols) ----
    {
        const int colg = tid & 63;
        const int rq   = tid >> 6;       // 0..7
        const float* src = v_in + ((size_t)b * (3 * CC)) * NPTS + n0 + colg;
        #pragma unroll 4
        for (int it = 0; it < 48; it++) {
            int r = rq + it * 8;
            A[r * TN + colg] = src[(size_t)r * NPTS];
        }
        const float* ssrc = s_in + ((size_t)b * CC) * NPTS + n0 + colg;
        #pragma unroll 4
        for (int it = 0; it < 16; it++) {
            int r = rq + it * 8;
            Bm[r * TN + colg] = ssrc[(size_t)r * NPTS];
        }
    }
    __syncthreads();

    // ---- x channel mean; center A in place ----
    float mx[NSL], my[NSL], mz[NSL];
    {
        ull px2 = 0, py2 = 0, pz2 = 0;
        #pragma unroll
        for (int j = 0; j < OPT; j++) {
            int c = ob + j;
            ADD2(px2, px2, lds2(&A[(3 * c + 0) * TN + cb]));
            ADD2(py2, py2, lds2(&A[(3 * c + 1) * TN + cb]));
            ADD2(pz2, pz2, lds2(&A[(3 * c + 2) * TN + cb]));
        }
        sts2(&red[(og * 6 + 0) * TN + cb], px2);
        sts2(&red[(og * 6 + 1) * TN + cb], py2);
        sts2(&red[(og * 6 + 2) * TN + cb], pz2);
    }
    __syncthreads();
    ull mx2 = 0, my2 = 0, mz2 = 0;
    #pragma unroll
    for (int g = 0; g < NG; g++) {
        ADD2(mx2, mx2, lds2(&red[(g * 6 + 0) * TN + cb]));
        ADD2(my2, my2, lds2(&red[(g * 6 + 1) * TN + cb]));
        ADD2(mz2, mz2, lds2(&red[(g * 6 + 2) * TN + cb]));
    }
    __syncthreads();
    #pragma unroll
    for (int s = 0; s < NSL; s++) {
        mx[s] = (s ? hi2(mx2) : lo2(mx2)) * (1.f / CC);
        my[s] = (s ? hi2(my2) : lo2(my2)) * (1.f / CC);
        mz[s] = (s ? hi2(mz2) : lo2(mz2)) * (1.f / CC);
    }
    {
        ull nmx = pack2(-mx[0], -mx[1]), nmy = pack2(-my[0], -my[1]), nmz = pack2(-mz[0], -mz[1]);
        #pragma unroll
        for (int j = 0; j < OPT; j++) {
            int c = ob + j;
            ull v;
            v = lds2(&A[(3 * c + 0) * TN + cb]); ADD2(v, v, nmx); sts2(&A[(3 * c + 0) * TN + cb], v);
            v = lds2(&A[(3 * c + 1) * TN + cb]); ADD2(v, v, nmy); sts2(&A[(3 * c + 1) * TN + cb], v);
            v = lds2(&A[(3 * c + 2) * TN + cb]); ADD2(v, v, nmz); sts2(&A[(3 * c + 2) * TN + cb], v);
        }
    }
    __syncthreads();

    ull aX[NSL][OP2], aY[NSL][OP2], aZ[NSL][OP2];

    // ================= scalar branch =================
    // dd = vsdir_weight @ x_c
    gemm3<true>(g_vsdWt, A, cb, ob, aX, aY, aZ);
    float tvv[NSL][OPT];
    {
        float pq[NSL] = {0.f, 0.f};
        #pragma unroll
        for (int jj = 0; jj < OPT; jj++) {
            int o = ob + jj;
            ull xp = lds2(&A[(3 * o + 0) * TN + cb]);
            ull yp = lds2(&A[(3 * o + 1) * TN + cb]);
            ull zp = lds2(&A[(3 * o + 2) * TN + cb]);
            #pragma unroll
            for (int s = 0; s < NSL; s++) {
                float ux = GETA(aX, s, jj), uy = GETA(aY, s, jj), uz = GETA(aZ, s, jj);
                float n2 = ux * ux + uy * uy + uz * uz;
                float inv = rsq_guard(n2);
                float vx = s ? hi2(xp) : lo2(xp);
                float vy = s ? hi2(yp) : lo2(yp);
                float vz = s ? hi2(zp) : lo2(zp);
                float q = (vx * ux + vy * uy + vz * uz) * inv;
                tvv[s][jj] = q;
                pq[s] += q * q;
            }
        }
        sts2(&red[og * TN + cb], pack2(pq[0], pq[1]));
    }
    __syncthreads();
    ull Q2 = 0;
    #pragma unroll
    for (int g = 0; g < NG; g++) ADD2(Q2, Q2, lds2(&red[g * TN + cb]));
    __syncthreads();
    {
        float qinv[NSL];
        qinv[0] = rsq_guard(lo2(Q2));
        qinv[1] = rsq_guard(hi2(Q2));
        #pragma unroll
        for (int jj = 0; jj < OPT; jj++)
            sts2(&Bm[(CC + ob + jj) * TN + cb], pack2(tvv[0][jj] * qinv[0], tvv[1][jj] * qinv[1]));
    }
    __syncthreads();

    // s_out = vs_W @ p + vs_b + ss_W @ s + ss_b  ; fused: t = sv_W @ s + sv_b
    ull t2[NSL][OP2];
    {
        ull so2[NSL][OP2];
        #pragma unroll
        for (int j = 0; j < OP2; j++) {
            ull bj = pack2(vs_b[ob + 2 * j] + ss_b[ob + 2 * j],
                           vs_b[ob + 2 * j + 1] + ss_b[ob + 2 * j + 1]);
            so2[0][j] = bj; so2[1][j] = bj;
            ull tj = pack2(sv_b[ob + 2 * j], sv_b[ob + 2 * j + 1]);
            t2[0][j] = tj; t2[1][j] = tj;
        }
        #pragma unroll 2
        for (int c = 0; c < CC; c++) {
            ull pp = lds2(&Bm[(CC + c) * TN + cb]);
            ull sp = lds2(&Bm[c * TN + cb]);
            ull p0, p1, s0, s1;
            PACK_DUP(p0, lo2(pp)); PACK_DUP(p1, hi2(pp));
            PACK_DUP(s0, lo2(sp)); PACK_DUP(s1, hi2(sp));
            ull wva[OP2], wvb[OP2], wsv[OP2];
            load_w4x2(&g_vsWt[c * CC + ob], wva);
            load_w4x2(&g_ssWt[c * CC + ob], wvb);
            load_w4x2(&g_svWt[c * CC + ob], wsv);
            #pragma unroll
            for (int j = 0; j < OP2; j++) {
                FMA2(so2[0][j], wva[j], p0); FMA2(so2[1][j], wva[j], p1);
                FMA2(so2[0][j], wvb[j], s0); FMA2(so2[1][j], wvb[j], s1);
                FMA2(t2[0][j],  wsv[j], s0); FMA2(t2[1][j],  wsv[j], s1);
            }
        }
        float* outs = out + (size_t)B * CC * 3 * NPTS + ((size_t)b * CC) * NPTS + n0 + cb;
        #pragma unroll
        for (int j = 0; j < OP2; j++) {
            *(ull*)&outs[(size_t)(ob + 2 * j) * NPTS]     = pack2(lo2(so2[0][j]), lo2(so2[1][j]));
            *(ull*)&outs[(size_t)(ob + 2 * j + 1) * NPTS] = pack2(hi2(so2[0][j]), hi2(so2[1][j]));
        }
    }

    // ================= vector branch =================
    // ---- u_c = W1 @ x_c ----
    gemm3<true>(g_W1t, A, cb, ob, aX, aY, aZ);
    {
        float pu[NSL][4];
        #pragma unroll
        for (int s = 0; s < NSL; s++) {
            ull sx = 0, sy = 0, sz = 0, st = 0;
            #pragma unroll
            for (int j = 0; j < OP2; j++) {
                ADD2(sx, sx, aX[s][j]); ADD2(sy, sy, aY[s][j]); ADD2(sz, sz, aZ[s][j]);
                FMA2(st, t2[s][j], t2[s][j]);
            }
            pu[s][0] = lo2(sx) + hi2(sx); pu[s][1] = lo2(sy) + hi2(sy);
            pu[s][2] = lo2(sz) + hi2(sz); pu[s][3] = lo2(st) + hi2(st);
        }
        sts2(&red[(og * 6 + 0) * TN + cb], pack2(pu[0][0], pu[1][0]));
        sts2(&red[(og * 6 + 1) * TN + cb], pack2(pu[0][1], pu[1][1]));
        sts2(&red[(og * 6 + 2) * TN + cb], pack2(pu[0][2], pu[1][2]));
        sts2(&red[(og * 6 + 3) * TN + cb], pack2(pu[0][3], pu[1][3]));
    }
    __syncthreads();
    float mux[NSL], muy[NSL], muz[NSL], tinv[NSL];
    {
        ull sx = 0, sy = 0, sz = 0, st = 0;
        #pragma unroll
        for (int g = 0; g < NG; g++) {
            ADD2(sx, sx, lds2(&red[(g * 6 + 0) * TN + cb]));
            ADD2(sy, sy, lds2(&red[(g * 6 + 1) * TN + cb]));
            ADD2(sz, sz, lds2(&red[(g * 6 + 2) * TN + cb]));
            ADD2(st, st, lds2(&red[(g * 6 + 3) * TN + cb]));
        }
        #pragma unroll
        for (int s = 0; s < NSL; s++) {
            mux[s] = (s ? hi2(sx) : lo2(sx)) * (1.f / CC);
            muy[s] = (s ? hi2(sy) : lo2(sy)) * (1.f / CC);
            muz[s] = (s ? hi2(sz) : lo2(sz)) * (1.f / CC);
            tinv[s] = rsq_guard(s ? hi2(st) : lo2(st));
        }
    }
    __syncthreads();

    // v1 = (u_c - mu)*s2v + (mu + m) -> Bm; partial v1-mean
    float p1x[NSL] = {0.f, 0.f}, p1y[NSL] = {0.f, 0.f}, p1z[NSL] = {0.f, 0.f};
    #pragma unroll
    for (int jj = 0; jj < OPT; jj++) {
        int o = ob + jj;
        float av[NSL][3];
        #pragma unroll
        for (int s = 0; s < NSL; s++) {
            float s2v = ((jj & 1) ? hi2(t2[s][jj >> 1]) : lo2(t2[s][jj >> 1])) * tinv[s];
            av[s][0] = fmaf(GETA(aX, s, jj) - mux[s], s2v, mux[s] + mx[s]);
            av[s][1] = fmaf(GETA(aY, s, jj) - muy[s], s2v, muy[s] + my[s]);
            av[s][2] = fmaf(GETA(aZ, s, jj) - muz[s], s2v, muz[s] + mz[s]);
            p1x[s] += av[s][0]; p1y[s] += av[s][1]; p1z[s] += av[s][2];
        }
        sts2(&Bm[(3 * o + 0) * TN + cb], pack2(av[0][0], av[1][0]));
        sts2(&Bm[(3 * o + 1) * TN + cb], pack2(av[0][1], av[1][1]));
        sts2(&Bm[(3 * o + 2) * TN + cb], pack2(av[0][2], av[1][2]));
    }

    // ---- d_c = W2 @ x_c ----
    gemm3<true>(g_W2t, A, cb, ob, aX, aY, aZ);
    {
        float pd[NSL][3];
        #pragma unroll
        for (int s = 0; s < NSL; s++) {
            ull sx = 0, sy = 0, sz = 0;
            #pragma unroll
            for (int j = 0; j < OP2; j++) {
                ADD2(sx, sx, aX[s][j]); ADD2(sy, sy, aY[s][j]); ADD2(sz, sz, aZ[s][j]);
            }
            pd[s][0] = lo2(sx) + hi2(sx); pd[s][1] = lo2(sy) + hi2(sy); pd[s][2] = lo2(sz) + hi2(sz);
        }
        sts2(&red[(og * 6 + 0) * TN + cb], pack2(pd[0][0], pd[1][0]));
        sts2(&red[(og * 6 + 1) * TN + cb], pack2(pd[0][1], pd[1][1]));
        sts2(&red[(og * 6 + 2) * TN + cb], pack2(pd[0][2], pd[1][2]));
        sts2(&red[(og * 6 + 3) * TN + cb], pack2(p1x[0], p1x[1]));
        sts2(&red[(og * 6 + 4) * TN + cb], pack2(p1y[0], p1y[1]));
        sts2(&red[(og * 6 + 5) * TN + cb], pack2(p1z[0], p1z[1]));
    }
    __syncthreads();
    float dmx[NSL], dmy[NSL], dmz[NSL], m1x[NSL], m1y[NSL], m1z[NSL];
    {
        ull sx = 0, sy = 0, sz = 0, s1x = 0, s1y = 0, s1z = 0;
        #pragma unroll
        for (int g = 0; g < NG; g++) {
            ADD2(sx,  sx,  lds2(&red[(g * 6 + 0) * TN + cb]));
            ADD2(sy,  sy,  lds2(&red[(g * 6 + 1) * TN + cb]));
            ADD2(sz,  sz,  lds2(&red[(g * 6 + 2) * TN + cb]));
            ADD2(s1x, s1x, lds2(&red[(g * 6 + 3) * TN + cb]));
            ADD2(s1y, s1y, lds2(&red[(g * 6 + 4) * TN + cb]));
            ADD2(s1z, s1z, lds2(&red[(g * 6 + 5) * TN + cb]));
        }
        #pragma unroll
        for (int s = 0; s < NSL; s++) {
            dmx[s] = (s ? hi2(sx)  : lo2(sx))  * (1.f / CC);
            dmy[s] = (s ? hi2(sy)  : lo2(sy))  * (1.f / CC);
            dmz[s] = (s ? hi2(sz)  : lo2(sz))  * (1.f / CC);
            m1x[s] = (s ? hi2(s1x) : lo2(s1x)) * (1.f / CC);
            m1y[s] = (s ? hi2(s1y) : lo2(s1y)) * (1.f / CC);
            m1z[s] = (s ? hi2(s1z) : lo2(s1z)) * (1.f / CC);
        }
    }
    __syncthreads();

    // ---- center d; per-channel n2; sumsq over channels ----
    ull nn2[NSL][OP2];
    {
        float pl[NSL];
        #pragma unroll
        for (int s = 0; s < NSL; s++) {
            ull ndx, ndy, ndz;
            PACK_DUP(ndx, -dmx[s]); PACK_DUP(ndy, -dmy[s]); PACK_DUP(ndz, -dmz[s]);
            ull plsum = 0;
            #pragma unroll
            for (int j = 0; j < OP2; j++) {
                ADD2(aX[s][j], aX[s][j], ndx);
                ADD2(aY[s][j], aY[s][j], ndy);
                ADD2(aZ[s][j], aZ[s][j], ndz);
                ull n2 = 0;
                FMA2(n2, aX[s][j], aX[s][j]);
                FMA2(n2, aY[s][j], aY[s][j]);
                FMA2(n2, aZ[s][j], aZ[s][j]);
                nn2[s][j] = n2;
                ADD2(plsum, plsum, n2);
            }
            pl[s] = lo2(plsum) + hi2(plsum);
        }
        sts2(&red[og * TN + cb], pack2(pl[0], pl[1]));
    }
    __syncthreads();
    float linv[NSL];
    {
        ull L2 = 0;
        #pragma unroll
        for (int g = 0; g < NG; g++) ADD2(L2, L2, lds2(&red[g * TN + cb]));
        linv[0] = rsq_guard(lo2(L2));
        linv[1] = rsq_guard(hi2(L2));
    }
    __syncthreads();

    // ---- v_cross = cross(ceq, v1 - v1m) + v1 -> A ----
    #pragma unroll
    for (int jj = 0; jj < OPT; jj++) {
        int o = ob + jj;
        ull v1xp = lds2(&Bm[(3 * o + 0) * TN + cb]);
        ull v1yp = lds2(&Bm[(3 * o + 1) * TN + cb]);
        ull v1zp = lds2(&Bm[(3 * o + 2) * TN + cb]);
        float cx[NSL], cy[NSL], cz[NSL];
        #pragma unroll
        for (int s = 0; s < NSL; s++) {
            float n2 = (jj & 1) ? hi2(nn2[s][jj >> 1]) : lo2(nn2[s][jj >> 1]);
            float nyv = sqrtf(n2);
            // (nyv * linv) / max(nyv, eps)  ==  linv * min(nyv/eps, 1)
            float cf = linv[s] * fminf(nyv * (1.f / EPSV), 1.f);
            float ex = GETA(aX, s, jj) * cf;
            float ey = GETA(aY, s, jj) * cf;
            float ez = GETA(aZ, s, jj) * cf;
            float ax = s ? hi2(v1xp) : lo2(v1xp);
            float ay = s ? hi2(v1yp) : lo2(v1yp);
            float az = s ? hi2(v1zp) : lo2(v1zp);
            float wx = ax - m1x[s], wy = ay - m1y[s], wz = az - m1z[s];
            cx[s] = ey * wz - ez * wy + ax;
            cy[s] = ez * wx - ex * wz + ay;
            cz[s] = ex * wy - ey * wx + az;
        }
        sts2(&A[(3 * o + 0) * TN + cb], pack2(cx[0], cx[1]));
        sts2(&A[(3 * o + 1) * TN + cb], pack2(cy[0], cy[1]));
        sts2(&A[(3 * o + 2) * TN + cb], pack2(cz[0], cz[1]));
    }
    __syncthreads();

    // ---- v_out = W3[:, :128] @ v_cross (A) + W3[:, 128:] @ v1 (Bm) ----
    gemm3<true >(g_W3t,           A,  cb, ob, aX, aY, aZ);
    gemm3<false>(g_W3t + CC * CC, Bm, cb, ob, aX, aY, aZ);
    {
        float* outv = out + ((size_t)b * CC) * 3 * NPTS + n0 + cb;
        #pragma unroll
        for (int j = 0; j < OP2; j++) {
            int o0 = ob + 2 * j, o1 = o0 + 1;
            *(ull*)&outv[(size_t)(3 * o0 + 0) * NPTS] = pack2(lo2(aX[0][j]), lo2(aX[1][j]));
            *(ull*)&outv[(size_t)(3 * o0 + 1) * NPTS] = pack2(lo2(aY[0][j]), lo2(aY[1][j]));
            *(ull*)&outv[(size_t)(3 * o0 + 2) * NPTS] = pack2(lo2(aZ[0][j]), lo2(aZ[1][j]));
            *(ull*)&outv[(size_t)(3 * o1 + 0) * NPTS] = pack2(hi2(aX[0][j]), hi2(aX[1][j]));
            *(ull*)&outv[(size_t)(3 * o1 + 1) * NPTS] = pack2(hi2(aY[0][j]), hi2(aY[1][j]));
            *(ull*)&outv[(size_t)(3 * o1 + 2) * NPTS] = pack2(hi2(aZ[0][j]), hi2(aZ[1][j]));
        }
    }
}

extern "C" void kernel_launch(void* const* d_in, const int* in_sizes, int n_in,
                              void* d_out, int out_size)
{
    const float* v_in      = (const float*)d_in[0];
    const float* s_in      = (const float*)d_in[1];
    const float* weight    = (const float*)d_in[2];
    const float* sv_W      = (const float*)d_in[3];
    const float* sv_b      = (const float*)d_in[4];
    const float* cross_w   = (const float*)d_in[5];
    const float* crossfc_w = (const float*)d_in[6];
    const float* vsdir_w   = (const float*)d_in[7];
    const float* vs_W      = (const float*)d_in[8];
    const float* vs_b      = (const float*)d_in[9];
    const float* ss_W      = (const float*)d_in[10];
    const float* ss_b      = (const float*)d_in[11];
    float* out = (float*)d_out;

    const int B = in_sizes[0] / (CC * 3 * NPTS);   // 16

    prep_kernel<<<CC, CC>>>(weight, sv_W, cross_w, crossfc_w, vsdir_w, vs_W, ss_W);

    // smem: 2 * 384*64 + 96*64 floats = 221,184 B -> 1 block/SM, 16 warps
    const size_t smem = (size_t)(6 * CC * TN + 96 * TN) * sizeof(float);
    cudaFuncSetAttribute(fused_kernel, cudaFuncAttributeMaxDynamicSharedMemorySize, (int)smem);
    fused_kernel<<<B * (NPTS / TN), NTHR, smem>>>(v_in, s_in, sv_b, vs_b, ss_b, out, B);
}

// round 14
// speedup vs baseline: 1.5537x; 1.5537x over previous
#include <cuda_runtime.h>
#include <math.h>
#include <stdint.h>

#define CC   128
#define NPTS 4096
#define TN   64
#define NG   16
#define OPT  8
#define OP2  4
#define NSL  2
#define NTHR 512
#define EPSV 1e-12f

typedef unsigned long long ull;

// Pre-expanded (se3) + transposed weights: Wt[c][o] = W[o][c]
__device__ float g_W1t [CC * CC];
__device__ float g_W2t [CC * CC];
__device__ float g_W3t [2 * CC * CC];
__device__ float g_svWt[CC * CC];
__device__ float g_vsdWt[CC * CC];
__device__ float g_vsWt[CC * CC];
__device__ float g_ssWt[CC * CC];

__global__ void prep_kernel(const float* __restrict__ weight,
                            const float* __restrict__ sv_W,
                            const float* __restrict__ cross_weight,
                            const float* __restrict__ crossfc_weight,
                            const float* __restrict__ vsdir_weight,
                            const float* __restrict__ vs_W,
                            const float* __restrict__ ss_W)
{
    const int o = blockIdx.x;
    const int t = threadIdx.x;
    __shared__ float sred[128];

    float w = (t < CC - 1) ? weight[o * (CC - 1) + t] : 0.f;
    sred[t] = w; __syncthreads();
    for (int k = 64; k > 0; k >>= 1) { if (t < k) sred[t] += sred[t + k]; __syncthreads(); }
    float rs1 = sred[0]; __syncthreads();
    if (t < CC - 1) g_W1t[t * CC + o] = w;
    else            g_W1t[(CC - 1) * CC + o] = 1.f - rs1;

    float w2 = (t < CC - 1) ? cross_weight[o * (CC - 1) + t] : 0.f;
    sred[t] = w2; __syncthreads();
    for (int k = 64; k > 0; k >>= 1) { if (t < k) sred[t] += sred[t + k]; __syncthreads(); }
    float rs2 = sred[0]; __syncthreads();
    if (t < CC - 1) g_W2t[t * CC + o] = w2;
    else            g_W2t[(CC - 1) * CC + o] = 1.f - rs2;

    float a0 = crossfc_weight[o * (2 * CC - 1) + t];
    float a1 = (t < CC - 1) ? crossfc_weight[o * (2 * CC - 1) + CC + t] : 0.f;
    sred[t] = a0 + a1; __syncthreads();
    for (int k = 64; k > 0; k >>= 1) { if (t < k) sred[t] += sred[t + k]; __syncthreads(); }
    float rs3 = sred[0]; __syncthreads();
    g_W3t[t * CC + o] = a0;
    if (t < CC - 1) g_W3t[(CC + t) * CC + o] = a1;
    else            g_W3t[(2 * CC - 1) * CC + o] = 1.f - rs3;

    g_svWt [t * CC + o] = sv_W        [o * CC + t];
    g_vsdWt[t * CC + o] = vsdir_weight[o * CC + t];
    g_vsWt [t * CC + o] = vs_W        [o * CC + t];
    g_ssWt [t * CC + o] = ss_W        [o * CC + t];
}

// ---- packed f32x2 helpers ----
#define FMA2(acc, w, x) \
    asm("fma.rn.f32x2 %0, %1, %2, %3;" : "=l"(acc) : "l"(w), "l"(x), "l"(acc))
#define ADD2(d, a, b) \
    asm("add.rn.f32x2 %0, %1, %2;" : "=l"(d) : "l"(a), "l"(b))
#define PACK_DUP(out, x) \
    asm("mov.b64 %0, {%1, %1};" : "=l"(out) : "r"(__float_as_uint(x)))

__device__ __forceinline__ float lo2(ull v) { return __uint_as_float((unsigned)v); }
__device__ __forceinline__ float hi2(ull v) { return __uint_as_float((unsigned)(v >> 32)); }
__device__ __forceinline__ ull pack2(float lo, float hi) {
    return (ull)__float_as_uint(lo) | ((ull)__float_as_uint(hi) << 32);
}
__device__ __forceinline__ ull lds2(const float* p) { return *(const ull*)p; }
__device__ __forceinline__ void sts2(float* p, ull v) { *(ull*)p = v; }

// 1 / max(sqrt(x), EPSV) == rsqrt(max(x, EPSV^2))  (sqrt is monotone)
__device__ __forceinline__ float rsq_guard(float x) {
    return rsqrtf(fmaxf(x, 1e-24f));
}

// Load 8 consecutive transposed-weight floats as 4 packed u64 (2x LDG.128).
__device__ __forceinline__ void load_w4x2(const float* __restrict__ base, ull* w2)
{
    const ulonglong2* p = (const ulonglong2*)base;
    ulonglong2 a = p[0], b = p[1];
    w2[0] = a.x; w2[1] = a.y; w2[2] = b.x; w2[3] = b.y;
}

// GEMM over 3-vector tile S[384][TN]; accumulate 8 out-ch x 3 comps x 2 slots.
// unroll 4: ~4-k-step static window to hoist weight LDGs a full L2 latency.
template<bool INIT>
__device__ __forceinline__ void gemm3(const float* __restrict__ Wt,
                                      const float* __restrict__ S,
                                      int cb, int ob,
                                      ull aX[NSL][OP2], ull aY[NSL][OP2], ull aZ[NSL][OP2])
{
    if (INIT) {
        #pragma unroll
        for (int s = 0; s < NSL; s++)
            #pragma unroll
            for (int j = 0; j < OP2; j++) { aX[s][j] = 0; aY[s][j] = 0; aZ[s][j] = 0; }
    }
    #pragma unroll 4
    for (int c = 0; c < CC; c++) {
        ull xp = lds2(&S[(3 * c + 0) * TN + cb]);
        ull yp = lds2(&S[(3 * c + 1) * TN + cb]);
        ull zp = lds2(&S[(3 * c + 2) * TN + cb]);
        ull x0, x1, y0, y1, z0, z1;
        PACK_DUP(x0, lo2(xp)); PACK_DUP(x1, hi2(xp));
        PACK_DUP(y0, lo2(yp)); PACK_DUP(y1, hi2(yp));
        PACK_DUP(z0, lo2(zp)); PACK_DUP(z1, hi2(zp));
        ull w2[OP2]; load_w4x2(&Wt[c * CC + ob], w2);
        #pragma unroll
        for (int j = 0; j < OP2; j++) {
            FMA2(aX[0][j], w2[j], x0); FMA2(aX[1][j], w2[j], x1);
            FMA2(aY[0][j], w2[j], y0); FMA2(aY[1][j], w2[j], y1);
            FMA2(aZ[0][j], w2[j], z0); FMA2(aZ[1][j], w2[j], z1);
        }
    }
}

// value of channel (ob + jj) for slot s from packed accumulators
#define GETA(arr, s, jj) ((jj & 1) ? hi2(arr[s][jj >> 1]) : lo2(arr[s][jj >> 1]))

// ---------------------------------------------------------------------------
// Fused kernel: one block = one (b, 64-point) tile. 512 threads, 1 block/SM.
// Each thread: 8 output channels (og 0..15) x 2 adjacent points (cb, cb+1).
// ---------------------------------------------------------------------------
__global__ void __launch_bounds__(NTHR, 1)
fused_kernel(const float* __restrict__ v_in, const float* __restrict__ s_in,
             const float* __restrict__ sv_b, const float* __restrict__ vs_b,
             const float* __restrict__ ss_b, float* __restrict__ out, int B)
{
    extern __shared__ float sm[];
    float* A   = sm;                     // [384][64]  x_c, later v_cross
    float* Bm  = sm + 3 * CC * TN;       // [384][64]  s+p, later v1
    float* red = sm + 6 * CC * TN;       // [96][64]

    const int tid = threadIdx.x;
    const int nl  = tid & 31;
    const int og  = tid >> 5;            // 0..15
    const int ob  = og * OPT;
    const int cb  = nl * 2;              // column base (2 adjacent points)

    const int b  = blockIdx.x >> 6;      // 64 tiles per batch
    const int n0 = (blockIdx.x & 63) * TN;

    // ---- load x -> A, s -> Bm[0:128] (coalesced over 64 cols) ----
    {
        const int colg = tid & 63;
        const int rq   = tid >> 6;       // 0..7
        const float* src = v_in + ((size_t)b * (3 * CC)) * NPTS + n0 + colg;
        #pragma unroll 4
        for (int it = 0; it < 48; it++) {
            int r = rq + it * 8;
            A[r * TN + colg] = src[(size_t)r * NPTS];
        }
        const float* ssrc = s_in + ((size_t)b * CC) * NPTS + n0 + colg;
        #pragma unroll 4
        for (int it = 0; it < 16; it++) {
            int r = rq + it * 8;
            Bm[r * TN + colg] = ssrc[(size_t)r * NPTS];
        }
    }
    __syncthreads();

    // ---- x channel mean; center A in place ----
    float mx[NSL], my[NSL], mz[NSL];
    {
        ull px2 = 0, py2 = 0, pz2 = 0;
        #pragma unroll
        for (int j = 0; j < OPT; j++) {
            int c = ob + j;
            ADD2(px2, px2, lds2(&A[(3 * c + 0) * TN + cb]));
            ADD2(py2, py2, lds2(&A[(3 * c + 1) * TN + cb]));
            ADD2(pz2, pz2, lds2(&A[(3 * c + 2) * TN + cb]));
        }
        sts2(&red[(og * 6 + 0) * TN + cb], px2);
        sts2(&red[(og * 6 + 1) * TN + cb], py2);
        sts2(&red[(og * 6 + 2) * TN + cb], pz2);
    }
    __syncthreads();
    ull mx2 = 0, my2 = 0, mz2 = 0;
    #pragma unroll
    for (int g = 0; g < NG; g++) {
        ADD2(mx2, mx2, lds2(&red[(g * 6 + 0) * TN + cb]));
        ADD2(my2, my2, lds2(&red[(g * 6 + 1) * TN + cb]));
        ADD2(mz2, mz2, lds2(&red[(g * 6 + 2) * TN + cb]));
    }
    __syncthreads();
    #pragma unroll
    for (int s = 0; s < NSL; s++) {
        mx[s] = (s ? hi2(mx2) : lo2(mx2)) * (1.f / CC);
        my[s] = (s ? hi2(my2) : lo2(my2)) * (1.f / CC);
        mz[s] = (s ? hi2(mz2) : lo2(mz2)) * (1.f / CC);
    }
    {
        ull nmx = pack2(-mx[0], -mx[1]), nmy = pack2(-my[0], -my[1]), nmz = pack2(-mz[0], -mz[1]);
        #pragma unroll
        for (int j = 0; j < OPT; j++) {
            int c = ob + j;
            ull v;
            v = lds2(&A[(3 * c + 0) * TN + cb]); ADD2(v, v, nmx); sts2(&A[(3 * c + 0) * TN + cb], v);
            v = lds2(&A[(3 * c + 1) * TN + cb]); ADD2(v, v, nmy); sts2(&A[(3 * c + 1) * TN + cb], v);
            v = lds2(&A[(3 * c + 2) * TN + cb]); ADD2(v, v, nmz); sts2(&A[(3 * c + 2) * TN + cb], v);
        }
    }
    __syncthreads();

    ull aX[NSL][OP2], aY[NSL][OP2], aZ[NSL][OP2];

    // ================= scalar branch =================
    // dd = vsdir_weight @ x_c
    gemm3<true>(g_vsdWt, A, cb, ob, aX, aY, aZ);
    float tvv[NSL][OPT];
    {
        float pq[NSL] = {0.f, 0.f};
        #pragma unroll
        for (int jj = 0; jj < OPT; jj++) {
            int o = ob + jj;
            ull xp = lds2(&A[(3 * o + 0) * TN + cb]);
            ull yp = lds2(&A[(3 * o + 1) * TN + cb]);
            ull zp = lds2(&A[(3 * o + 2) * TN + cb]);
            #pragma unroll
            for (int s = 0; s < NSL; s++) {
                float ux = GETA(aX, s, jj), uy = GETA(aY, s, jj), uz = GETA(aZ, s, jj);
                float n2 = ux * ux + uy * uy + uz * uz;
                float inv = rsq_guard(n2);
                float vx = s ? hi2(xp) : lo2(xp);
                float vy = s ? hi2(yp) : lo2(yp);
                float vz = s ? hi2(zp) : lo2(zp);
                float q = (vx * ux + vy * uy + vz * uz) * inv;
                tvv[s][jj] = q;
                pq[s] += q * q;
            }
        }
        sts2(&red[og * TN + cb], pack2(pq[0], pq[1]));
    }
    __syncthreads();
    ull Q2 = 0;
    #pragma unroll
    for (int g = 0; g < NG; g++) ADD2(Q2, Q2, lds2(&red[g * TN + cb]));
    __syncthreads();
    {
        float qinv[NSL];
        qinv[0] = rsq_guard(lo2(Q2));
        qinv[1] = rsq_guard(hi2(Q2));
        #pragma unroll
        for (int jj = 0; jj < OPT; jj++)
            sts2(&Bm[(CC + ob + jj) * TN + cb], pack2(tvv[0][jj] * qinv[0], tvv[1][jj] * qinv[1]));
    }
    __syncthreads();

    // s_out = vs_W @ p + vs_b + ss_W @ s + ss_b
    {
        ull so2[NSL][OP2];
        #pragma unroll
        for (int j = 0; j < OP2; j++) {
            ull bj = pack2(vs_b[ob + 2 * j] + ss_b[ob + 2 * j],
                           vs_b[ob + 2 * j + 1] + ss_b[ob + 2 * j + 1]);
            so2[0][j] = bj; so2[1][j] = bj;
        }
        #pragma unroll 4
        for (int c = 0; c < CC; c++) {
            ull pp = lds2(&Bm[(CC + c) * TN + cb]);
            ull sp = lds2(&Bm[c * TN + cb]);
            ull p0, p1, s0, s1;
            PACK_DUP(p0, lo2(pp)); PACK_DUP(p1, hi2(pp));
            PACK_DUP(s0, lo2(sp)); PACK_DUP(s1, hi2(sp));
            ull wva[OP2], wvb[OP2];
            load_w4x2(&g_vsWt[c * CC + ob], wva);
            load_w4x2(&g_ssWt[c * CC + ob], wvb);
            #pragma unroll
            for (int j = 0; j < OP2; j++) {
                FMA2(so2[0][j], wva[j], p0); FMA2(so2[1][j], wva[j], p1);
                FMA2(so2[0][j], wvb[j], s0); FMA2(so2[1][j], wvb[j], s1);
            }
        }
        float* outs = out + (size_t)B * CC * 3 * NPTS + ((size_t)b * CC) * NPTS + n0 + cb;
        #pragma unroll
        for (int j = 0; j < OP2; j++) {
            *(ull*)&outs[(size_t)(ob + 2 * j) * NPTS]     = pack2(lo2(so2[0][j]), lo2(so2[1][j]));
            *(ull*)&outs[(size_t)(ob + 2 * j + 1) * NPTS] = pack2(hi2(so2[0][j]), hi2(so2[1][j]));
        }
    }

    // ---- t = sv_W @ s + sv_b ----
    ull t2[NSL][OP2];
    {
        #pragma unroll
        for (int j = 0; j < OP2; j++) {
            ull bj = pack2(sv_b[ob + 2 * j], sv_b[ob + 2 * j + 1]);
            t2[0][j] = bj; t2[1][j] = bj;
        }
        #pragma unroll 4
        for (int c = 0; c < CC; c++) {
            ull sp = lds2(&Bm[c * TN + cb]);
            ull s0, s1;
            PACK_DUP(s0, lo2(sp)); PACK_DUP(s1, hi2(sp));
            ull w2[OP2]; load_w4x2(&g_svWt[c * CC + ob], w2);
            #pragma unroll
            for (int j = 0; j < OP2; j++) {
                FMA2(t2[0][j], w2[j], s0); FMA2(t2[1][j], w2[j], s1);
            }
        }
    }

    // ================= vector branch =================
    // ---- u_c = W1 @ x_c ----
    gemm3<true>(g_W1t, A, cb, ob, aX, aY, aZ);
    {
        float pu[NSL][4];
        #pragma unroll
        for (int s = 0; s < NSL; s++) {
            ull sx = 0, sy = 0, sz = 0, st = 0;
            #pragma unroll
            for (int j = 0; j < OP2; j++) {
                ADD2(sx, sx, aX[s][j]); ADD2(sy, sy, aY[s][j]); ADD2(sz, sz, aZ[s][j]);
                FMA2(st, t2[s][j], t2[s][j]);
            }
            pu[s][0] = lo2(sx) + hi2(sx); pu[s][1] = lo2(sy) + hi2(sy);
            pu[s][2] = lo2(sz) + hi2(sz); pu[s][3] = lo2(st) + hi2(st);
        }
        sts2(&red[(og * 6 + 0) * TN + cb], pack2(pu[0][0], pu[1][0]));
        sts2(&red[(og * 6 + 1) * TN + cb], pack2(pu[0][1], pu[1][1]));
        sts2(&red[(og * 6 + 2) * TN + cb], pack2(pu[0][2], pu[1][2]));
        sts2(&red[(og * 6 + 3) * TN + cb], pack2(pu[0][3], pu[1][3]));
    }
    __syncthreads();
    float mux[NSL], muy[NSL], muz[NSL], tinv[NSL];
    {
        ull sx = 0, sy = 0, sz = 0, st = 0;
        #pragma unroll
        for (int g = 0; g < NG; g++) {
            ADD2(sx, sx, lds2(&red[(g * 6 + 0) * TN + cb]));
            ADD2(sy, sy, lds2(&red[(g * 6 + 1) * TN + cb]));
            ADD2(sz, sz, lds2(&red[(g * 6 + 2) * TN + cb]));
            ADD2(st, st, lds2(&red[(g * 6 + 3) * TN + cb]));
        }
        #pragma unroll
        for (int s = 0; s < NSL; s++) {
            mux[s] = (s ? hi2(sx) : lo2(sx)) * (1.f / CC);
            muy[s] = (s ? hi2(sy) : lo2(sy)) * (1.f / CC);
            muz[s] = (s ? hi2(sz) : lo2(sz)) * (1.f / CC);
            tinv[s] = rsq_guard(s ? hi2(st) : lo2(st));
        }
    }
    __syncthreads();

    // v1 = (u_c - mu)*s2v + (mu + m) -> Bm; partial v1-mean
    float p1x[NSL] = {0.f, 0.f}, p1y[NSL] = {0.f, 0.f}, p1z[NSL] = {0.f, 0.f};
    #pragma unroll
    for (int jj = 0; jj < OPT; jj++) {
        int o = ob + jj;
        float av[NSL][3];
        #pragma unroll
        for (int s = 0; s < NSL; s++) {
            float s2v = ((jj & 1) ? hi2(t2[s][jj >> 1]) : lo2(t2[s][jj >> 1])) * tinv[s];
            av[s][0] = fmaf(GETA(aX, s, jj) - mux[s], s2v, mux[s] + mx[s]);
            av[s][1] = fmaf(GETA(aY, s, jj) - muy[s], s2v, muy[s] + my[s]);
            av[s][2] = fmaf(GETA(aZ, s, jj) - muz[s], s2v, muz[s] + mz[s]);
            p1x[s] += av[s][0]; p1y[s] += av[s][1]; p1z[s] += av[s][2];
        }
        sts2(&Bm[(3 * o + 0) * TN + cb], pack2(av[0][0], av[1][0]));
        sts2(&Bm[(3 * o + 1) * TN + cb], pack2(av[0][1], av[1][1]));
        sts2(&Bm[(3 * o + 2) * TN + cb], pack2(av[0][2], av[1][2]));
    }

    // ---- d_c = W2 @ x_c ----
    gemm3<true>(g_W2t, A, cb, ob, aX, aY, aZ);
    {
        float pd[NSL][3];
        #pragma unroll
        for (int s = 0; s < NSL; s++) {
            ull sx = 0, sy = 0, sz = 0;
            #pragma unroll
            for (int j = 0; j < OP2; j++) {
                ADD2(sx, sx, aX[s][j]); ADD2(sy, sy, aY[s][j]); ADD2(sz, sz, aZ[s][j]);
            }
            pd[s][0] = lo2(sx) + hi2(sx); pd[s][1] = lo2(sy) + hi2(sy); pd[s][2] = lo2(sz) + hi2(sz);
        }
        sts2(&red[(og * 6 + 0) * TN + cb], pack2(pd[0][0], pd[1][0]));
        sts2(&red[(og * 6 + 1) * TN + cb], pack2(pd[0][1], pd[1][1]));
        sts2(&red[(og * 6 + 2) * TN + cb], pack2(pd[0][2], pd[1][2]));
        sts2(&red[(og * 6 + 3) * TN + cb], pack2(p1x[0], p1x[1]));
        sts2(&red[(og * 6 + 4) * TN + cb], pack2(p1y[0], p1y[1]));
        sts2(&red[(og * 6 + 5) * TN + cb], pack2(p1z[0], p1z[1]));
    }
    __syncthreads();
    float dmx[NSL], dmy[NSL], dmz[NSL], m1x[NSL], m1y[NSL], m1z[NSL];
    {
        ull sx = 0, sy = 0, sz = 0, s1x = 0, s1y = 0, s1z = 0;
        #pragma unroll
        for (int g = 0; g < NG; g++) {
            ADD2(sx,  sx,  lds2(&red[(g * 6 + 0) * TN + cb]));
            ADD2(sy,  sy,  lds2(&red[(g * 6 + 1) * TN + cb]));
            ADD2(sz,  sz,  lds2(&red[(g * 6 + 2) * TN + cb]));
            ADD2(s1x, s1x, lds2(&red[(g * 6 + 3) * TN + cb]));
            ADD2(s1y, s1y, lds2(&red[(g * 6 + 4) * TN + cb]));
            ADD2(s1z, s1z, lds2(&red[(g * 6 + 5) * TN + cb]));
        }
        #pragma unroll
        for (int s = 0; s < NSL; s++) {
            dmx[s] = (s ? hi2(sx)  : lo2(sx))  * (1.f / CC);
            dmy[s] = (s ? hi2(sy)  : lo2(sy))  * (1.f / CC);
            dmz[s] = (s ? hi2(sz)  : lo2(sz))  * (1.f / CC);
            m1x[s] = (s ? hi2(s1x) : lo2(s1x)) * (1.f / CC);
            m1y[s] = (s ? hi2(s1y) : lo2(s1y)) * (1.f / CC);
            m1z[s] = (s ? hi2(s1z) : lo2(s1z)) * (1.f / CC);
        }
    }
    __syncthreads();

    // ---- center d; per-channel n2; sumsq over channels ----
    ull nn2[NSL][OP2];
    {
        float pl[NSL];
        #pragma unroll
        for (int s = 0; s < NSL; s++) {
            ull ndx, ndy, ndz;
            PACK_DUP(ndx, -dmx[s]); PACK_DUP(ndy, -dmy[s]); PACK_DUP(ndz, -dmz[s]);
            ull plsum = 0;
            #pragma unroll
            for (int j = 0; j < OP2; j++) {
                ADD2(aX[s][j], aX[s][j], ndx);
                ADD2(aY[s][j], aY[s][j], ndy);
                ADD2(aZ[s][j], aZ[s][j], ndz);
                ull n2 = 0;
                FMA2(n2, aX[s][j], aX[s][j]);
                FMA2(n2, aY[s][j], aY[s][j]);
                FMA2(n2, aZ[s][j], aZ[s][j]);
                nn2[s][j] = n2;
                ADD2(plsum, plsum, n2);
            }
            pl[s] = lo2(plsum) + hi2(plsum);
        }
        sts2(&red[og * TN + cb], pack2(pl[0], pl[1]));
    }
    __syncthreads();
    float linv[NSL];
    {
        ull L2 = 0;
        #pragma unroll
        for (int g = 0; g < NG; g++) ADD2(L2, L2, lds2(&red[g * TN + cb]));
        linv[0] = rsq_guard(lo2(L2));
        linv[1] = rsq_guard(hi2(L2));
    }
    __syncthreads();

    // ---- v_cross = cross(ceq, v1 - v1m) + v1 -> A ----
    #pragma unroll
    for (int jj = 0; jj < OPT; jj++) {
        int o = ob + jj;
        ull v1xp = lds2(&Bm[(3 * o + 0) * TN + cb]);
        ull v1yp = lds2(&Bm[(3 * o + 1) * TN + cb]);
        ull v1zp = lds2(&Bm[(3 * o + 2) * TN + cb]);
        float cx[NSL], cy[NSL], cz[NSL];
        #pragma unroll
        for (int s = 0; s < NSL; s++) {
            float n2 = (jj & 1) ? hi2(nn2[s][jj >> 1]) : lo2(nn2[s][jj >> 1]);
            float nyv = sqrtf(n2);
            // (nyv * linv) / max(nyv, eps)  ==  linv * min(nyv * 1e12, 1)
            float cf = linv[s] * fminf(nyv * (1.f / EPSV), 1.f);
            float ex = GETA(aX, s, jj) * cf;
            float ey = GETA(aY, s, jj) * cf;
            float ez = GETA(aZ, s, jj) * cf;
            float ax = s ? hi2(v1xp) : lo2(v1xp);
            float ay = s ? hi2(v1yp) : lo2(v1yp);
            float az = s ? hi2(v1zp) : lo2(v1zp);
            float wx = ax - m1x[s], wy = ay - m1y[s], wz = az - m1z[s];
            cx[s] = ey * wz - ez * wy + ax;
            cy[s] = ez * wx - ex * wz + ay;
            cz[s] = ex * wy - ey * wx + az;
        }
        sts2(&A[(3 * o + 0) * TN + cb], pack2(cx[0], cx[1]));
        sts2(&A[(3 * o + 1) * TN + cb], pack2(cy[0], cy[1]));
        sts2(&A[(3 * o + 2) * TN + cb], pack2(cz[0], cz[1]));
    }
    __syncthreads();

    // ---- v_out = W3[:, :128] @ v_cross (A) + W3[:, 128:] @ v1 (Bm) ----
    gemm3<true >(g_W3t,           A,  cb, ob, aX, aY, aZ);
    gemm3<false>(g_W3t + CC * CC, Bm, cb, ob, aX, aY, aZ);
    {
        float* outv = out + ((size_t)b * CC) * 3 * NPTS + n0 + cb;
        #pragma unroll
        for (int j = 0; j < OP2; j++) {
            int o0 = ob + 2 * j, o1 = o0 + 1;
            *(ull*)&outv[(size_t)(3 * o0 + 0) * NPTS] = pack2(lo2(aX[0][j]), lo2(aX[1][j]));
            *(ull*)&outv[(size_t)(3 * o0 + 1) * NPTS] = pack2(lo2(aY[0][j]), lo2(aY[1][j]));
            *(ull*)&outv[(size_t)(3 * o0 + 2) * NPTS] = pack2(lo2(aZ[0][j]), lo2(aZ[1][j]));
            *(ull*)&outv[(size_t)(3 * o1 + 0) * NPTS] = pack2(hi2(aX[0][j]), hi2(aX[1][j]));
            *(ull*)&outv[(size_t)(3 * o1 + 1) * NPTS] = pack2(hi2(aY[0][j]), hi2(aY[1][j]));
            *(ull*)&outv[(size_t)(3 * o1 + 2) * NPTS] = pack2(hi2(aZ[0][j]), hi2(aZ[1][j]));
        }
    }
}

extern "C" void kernel_launch(void* const* d_in, const int* in_sizes, int n_in,
                              void* d_out, int out_size)
{
    const float* v_in      = (const float*)d_in[0];
    const float* s_in      = (const float*)d_in[1];
    const float* weight    = (const float*)d_in[2];
    const float* sv_W      = (const float*)d_in[3];
    const float* sv_b      = (const float*)d_in[4];
    const float* cross_w   = (const float*)d_in[5];
    const float* crossfc_w = (const float*)d_in[6];
    const float* vsdir_w   = (const float*)d_in[7];
    const float* vs_W      = (const float*)d_in[8];
    const float* vs_b      = (const float*)d_in[9];
    const float* ss_W      = (const float*)d_in[10];
    const float* ss_b      = (const float*)d_in[11];
    float* out = (float*)d_out;

    const int B = in_sizes[0] / (CC * 3 * NPTS);   // 16

    prep_kernel<<<CC, CC>>>(weight, sv_W, cross_w, crossfc_w, vsdir_w, vs_W, ss_W);

    // smem: 2 * 384*64 + 96*64 floats = 221,184 B -> 1 block/SM, 16 warps
    const size_t smem = (size_t)(6 * CC * TN + 96 * TN) * sizeof(float);
    cudaFuncSetAttribute(fused_kernel, cudaFuncAttributeMaxDynamicSharedMemorySize, (int)smem);
    fused_kernel<<<B * (NPTS / TN), NTHR, smem>>>(v_in, s_in, sv_b, vs_b, ss_b, out, B);
}